// round 8
// baseline (speedup 1.0000x reference)
#include <cuda_runtime.h>
#include <cuda_fp16.h>
#include <cstdint>

#define KCODES 512
#define DCH 64
#define NPIX (32*64*64)        // 131072
#define TOTAL (NPIX*DCH)       // 8388608
#define TILE_M 128
#define NTILES (NPIX/TILE_M)   // 1024
#define TPB 256
#define REPAIR_T 1e-3f

// ---- smem byte offsets ----
#define SM_X    0           // fp16 X tile, 128 rows x 128B swizzled (16KB)
#define SM_E    16384       // fp16 E tile, 512 rows x 128B swizzled (64KB)
#define SM_E2V  81920       // float[512]
#define SM_X2V  83968       // float[128]
#define SM_RED  84480       // double[256]
#define SM_TD   0           // reuse X after MMA: float[2][128][3] = 3072B
#define SM_TI   3072        // int[2][128][3]   = 3072B
#define SMEM_BYTES 86528

__device__ double   g_partials[NTILES];
__device__ uint32_t gEimg[16384];   // 64KB preswizzled fp16 E image
__device__ float    gE2[KCODES];

__device__ __forceinline__ uint32_t smem_u32(const void* p) {
    uint32_t a;
    asm("{ .reg .u64 t; cvta.to.shared.u64 t, %1; cvt.u32.u64 %0, t; }" : "=r"(a) : "l"(p));
    return a;
}
__device__ __forceinline__ uint32_t sw(uint32_t row, uint32_t colb) {
    uint32_t off = row * 128u + colb;
    return off ^ ((off >> 3) & 0x70u);
}
__device__ __forceinline__ void ldsm4(uint32_t* r, uint32_t addr) {
    asm volatile("ldmatrix.sync.aligned.m8n8.x4.shared.b16 {%0,%1,%2,%3}, [%4];"
                 : "=r"(r[0]), "=r"(r[1]), "=r"(r[2]), "=r"(r[3]) : "r"(addr));
}
__device__ __forceinline__ void mma16816(float* c, const uint32_t* a, uint32_t b0, uint32_t b1) {
    asm volatile("mma.sync.aligned.m16n8k16.row.col.f32.f16.f16.f32 "
                 "{%0,%1,%2,%3},{%4,%5,%6,%7},{%8,%9},{%0,%1,%2,%3};"
                 : "+f"(c[0]), "+f"(c[1]), "+f"(c[2]), "+f"(c[3])
                 : "r"(a[0]), "r"(a[1]), "r"(a[2]), "r"(a[3]), "r"(b0), "r"(b1));
}
__device__ __forceinline__ bool better(float d, int i, float D, int I) {
    return (d < D) || (d == D && i < I);
}
// sorted top-3 insert
__device__ __forceinline__ void ins3(float d, int i, float* td, int* ti) {
    if (better(d, i, td[2], ti[2])) {
        if (better(d, i, td[1], ti[1])) {
            td[2] = td[1]; ti[2] = ti[1];
            if (better(d, i, td[0], ti[0])) { td[1] = td[0]; ti[1] = ti[0]; td[0] = d; ti[0] = i; }
            else { td[1] = d; ti[1] = i; }
        } else { td[2] = d; ti[2] = i; }
    }
}

// ---- prep: build preswizzled fp16 E image + e2 (runs once per call, 512 rows) ----
__global__ void vq_prep(const float* __restrict__ W) {
    int r = blockIdx.x * blockDim.x + threadIdx.x;   // 4 x 128 = 512
    if (r >= KCODES) return;
    float e2 = 0.0f;
    #pragma unroll 8
    for (int c2 = 0; c2 < 32; c2++) {
        float2 wv = *(const float2*)(W + r * DCH + c2 * 2);
        // e2 pairwise like R1 (passed): fma(x,x, y*y) accumulated
        e2 = __fadd_rn(e2, __fmaf_rn(wv.x, wv.x, __fmul_rn(wv.y, wv.y)));
        __half h0 = __float2half_rn(wv.x), h1 = __float2half_rn(wv.y);
        uint32_t pk = (uint32_t)__half_as_ushort(h0) | ((uint32_t)__half_as_ushort(h1) << 16);
        gEimg[sw((uint32_t)r, (uint32_t)c2 * 4) >> 2] = pk;
    }
    gE2[r] = e2;
}

__global__ __launch_bounds__(TPB, 2)
void vq_mma(const float* __restrict__ lat, const float* __restrict__ W,
            float* __restrict__ out) {
    extern __shared__ char smem[];
    const uint32_t sb = smem_u32(smem);
    const int tid = threadIdx.x, wid = tid >> 5, lane = tid & 31;
    float* sE2v = (float*)(smem + SM_E2V);
    float* sX2v = (float*)(smem + SM_X2V);

    // ---- Phase 1: warps 0-3 build X fp16 tile + x2; warps 4-7 copy E image + e2 ----
    if (tid < 128) {
        const int r = tid;
        const int n0 = blockIdx.x * TILE_M + r;
        const int base = (n0 >> 12) << 18;
        const int p = n0 & 4095;
        float x2 = 0.0f;
        #pragma unroll 8
        for (int c = 0; c < DCH; c++) {
            float v = lat[base + (c << 12) + p];
            x2 = __fadd_rn(x2, __fmul_rn(v, v));   // sequential, reference order
            *(__half*)(smem + SM_X + sw(r, c * 2)) = __float2half_rn(v);
        }
        sX2v[r] = x2;
    } else {
        const int t = tid - 128;                   // 0..127
        float4* dst = (float4*)(smem + SM_E);
        const float4* src = (const float4*)gEimg;
        #pragma unroll
        for (int i = 0; i < 32; i++) dst[t + i * 128] = src[t + i * 128];
        #pragma unroll
        for (int i = 0; i < 4; i++) sE2v[t + i * 128] = gE2[t + i * 128];
    }
    __syncthreads();

    // ---- Phase 2: fp16 mma.sync distances, per-thread top-3 on g = e2 - 2*dot ----
    const int mg = wid >> 1, ng = wid & 1;
    const int mbase = mg * 32, nbase = ng * 256;

    float td[4][3]; int ti[4][3];
    #pragma unroll
    for (int s = 0; s < 4; s++) {
        #pragma unroll
        for (int q = 0; q < 3; q++) { td[s][q] = 3.4e38f; ti[s][q] = 0x7FFFFFFF; }
    }

    const uint32_t aRow = (uint32_t)(mbase + (lane & 7) + (((lane >> 3) & 1) << 3));
    const uint32_t aKb  = (uint32_t)(((lane >> 4) & 1) << 4);
    const uint32_t bRowL = (uint32_t)((lane & 7) + (((lane >> 4) & 1) << 3));
    const uint32_t bKb  = (uint32_t)(((lane >> 3) & 1) << 4);

    #pragma unroll 1
    for (int chunk = 0; chunk < 4; chunk++) {
        const int cbase = nbase + chunk * 64;
        #pragma unroll
        for (int ntg = 0; ntg < 2; ntg++) {
            float acc[2][4][4];
            #pragma unroll
            for (int mt = 0; mt < 2; mt++)
                #pragma unroll
                for (int nt = 0; nt < 4; nt++)
                    #pragma unroll
                    for (int q = 0; q < 4; q++) acc[mt][nt][q] = 0.0f;

            #pragma unroll
            for (int ks = 0; ks < 4; ks++) {
                const uint32_t kb = (uint32_t)(ks * 32);
                uint32_t a[8], b[8];
                #pragma unroll
                for (int jjl = 0; jjl < 2; jjl++) {
                    int jj = ntg * 2 + jjl;
                    ldsm4(&b[jjl * 4], sb + SM_E + sw((uint32_t)(cbase + 16 * jj) + bRowL, kb + bKb));
                }
                ldsm4(&a[0], sb + SM_X + sw(aRow, kb + aKb));
                ldsm4(&a[4], sb + SM_X + sw(aRow + 16, kb + aKb));
                #pragma unroll
                for (int mt = 0; mt < 2; mt++)
                    #pragma unroll
                    for (int nt = 0; nt < 4; nt++) {
                        int j4 = (nt >> 1) * 4 + (nt & 1) * 2;
                        mma16816(acc[mt][nt], &a[mt * 4], b[j4], b[j4 + 1]);
                    }
            }
            // epilogue for this ntg: g = fl(e2 - 2*dot), track top-3 per rowset
            #pragma unroll
            for (int nt = 0; nt < 4; nt++) {
                const int col0 = cbase + 8 * (ntg * 4 + nt) + 2 * (lane & 3);
                const float e2a = sE2v[col0], e2b = sE2v[col0 + 1];
                #pragma unroll
                for (int mt = 0; mt < 2; mt++) {
                    float g00 = __fmaf_rn(-2.0f, acc[mt][nt][0], e2a);
                    float g01 = __fmaf_rn(-2.0f, acc[mt][nt][1], e2b);
                    float g10 = __fmaf_rn(-2.0f, acc[mt][nt][2], e2a);
                    float g11 = __fmaf_rn(-2.0f, acc[mt][nt][3], e2b);
                    ins3(g00, col0,     td[mt * 2],     ti[mt * 2]);
                    ins3(g01, col0 + 1, td[mt * 2],     ti[mt * 2]);
                    ins3(g10, col0,     td[mt * 2 + 1], ti[mt * 2 + 1]);
                    ins3(g11, col0 + 1, td[mt * 2 + 1], ti[mt * 2 + 1]);
                }
            }
        }
    }

    // ---- quad merge (lanes xor 1, 2 hold disjoint cols of same rows) ----
    #pragma unroll
    for (int st = 1; st <= 2; st <<= 1) {
        #pragma unroll
        for (int s = 0; s < 4; s++) {
            float od[3]; int oi[3];
            #pragma unroll
            for (int q = 0; q < 3; q++) {
                od[q] = __shfl_xor_sync(0xffffffffu, td[s][q], st);
                oi[q] = __shfl_xor_sync(0xffffffffu, ti[s][q], st);
            }
            #pragma unroll
            for (int q = 0; q < 3; q++) ins3(od[q], oi[q], td[s], ti[s]);
        }
    }

    __syncthreads();   // all ldsm X reads done -> X region reusable
    {
        float* sTd = (float*)(smem + SM_TD);
        int*   sTi = (int*)(smem + SM_TI);
        int s = lane & 3;
        int row = mbase + 8 * s + (lane >> 2);
        #pragma unroll
        for (int q = 0; q < 3; q++) {
            sTd[(ng * 128 + row) * 3 + q] = td[s][q];
            sTi[(ng * 128 + row) * 3 + q] = ti[s][q];
        }
    }
    __syncthreads();

    // ---- Phase 3: select (+ exact repair), gather, write, SSE ----
    double sse = 0.0;
    if (tid < 128) {
        const int r = tid;
        const int n0 = blockIdx.x * TILE_M + r;
        const int base = (n0 >> 12) << 18;
        const int p = n0 & 4095;
        const float x2 = sX2v[r];
        float* sTd = (float*)(smem + SM_TD);
        int*   sTi = (int*)(smem + SM_TI);

        float cd[6]; int ci[6];
        #pragma unroll
        for (int q = 0; q < 3; q++) {
            cd[q]     = sTd[r * 3 + q];         ci[q]     = sTi[r * 3 + q];
            cd[3 + q] = sTd[(128 + r) * 3 + q]; ci[3 + q] = sTi[(128 + r) * 3 + q];
        }
        // approx best1/best2 over 6
        float b1d = 3.4e38f, b2d = 3.4e38f; int b1i = 0x7FFFFFFF, b2i = 0x7FFFFFFF;
        #pragma unroll
        for (int q = 0; q < 6; q++) {
            if (better(cd[q], ci[q], b1d, b1i)) { b2d = b1d; b2i = b1i; b1d = cd[q]; b1i = ci[q]; }
            else if (better(cd[q], ci[q], b2d, b2i)) { b2d = cd[q]; b2i = ci[q]; }
        }
        int i1 = b1i;
        if (b2d - b1d < REPAIR_T) {
            // exact fp32 reference-rounded dist over all 6 candidates;
            // better() == ascending-index strict-< semantics
            float bestd = 3.4e38f; int besti = 0x7FFFFFFF;
            #pragma unroll 1
            for (int q = 0; q < 6; q++) {
                int k = ci[q];
                float dot = 0.0f;
                #pragma unroll 8
                for (int j = 0; j < DCH; j++)
                    dot = __fmaf_rn(lat[base + (j << 12) + p], W[k * DCH + j], dot);
                float d = __fmaf_rn(-2.0f, dot, __fadd_rn(x2, sE2v[k]));
                if (better(d, k, bestd, besti)) { bestd = d; besti = k; }
            }
            i1 = besti;
        }
        // gather + write + sse
        #pragma unroll 8
        for (int j = 0; j < DCH; j++) {
            float q = W[i1 * DCH + j];
            float xv = lat[base + (j << 12) + p];
            out[base + (j << 12) + p] = q;
            float df = q - xv;
            sse += (double)__fmul_rn(df, df);
        }
    }

    double* sRed = (double*)(smem + SM_RED);
    sRed[tid] = sse;
    __syncthreads();
    #pragma unroll
    for (int o = TPB / 2; o > 0; o >>= 1) {
        if (tid < o) sRed[tid] += sRed[tid + o];
        __syncthreads();
    }
    if (tid == 0) g_partials[blockIdx.x] = sRed[0];
}

__global__ void vq_finish(float* __restrict__ out, int out_size) {
    __shared__ double s[256];
    int t = threadIdx.x;
    double v = 0.0;
    #pragma unroll
    for (int i = 0; i < NTILES / 256; i++) v += g_partials[t + i * 256];
    s[t] = v;
    __syncthreads();
    #pragma unroll
    for (int o = 128; o > 0; o >>= 1) {
        if (t < o) s[t] += s[t + o];
        __syncthreads();
    }
    if (t == 0) {
        float m = (float)(s[0] / (double)TOTAL);
        out[out_size - 1] = __fadd_rn(__fmul_rn(m, 0.25f), m);
    }
}

extern "C" void kernel_launch(void* const* d_in, const int* in_sizes, int n_in,
                              void* d_out, int out_size) {
    const float* lat = (const float*)d_in[0];
    const float* W   = (const float*)d_in[1];
    float* out = (float*)d_out;

    cudaFuncSetAttribute(vq_mma, cudaFuncAttributeMaxDynamicSharedMemorySize, SMEM_BYTES);

    vq_prep<<<4, 128>>>(W);
    vq_mma<<<NTILES, TPB, SMEM_BYTES>>>(lat, W, out);
    vq_finish<<<1, 256>>>(out, out_size);
}

// round 15
// speedup vs baseline: 1.5498x; 1.5498x over previous
#include <cuda_runtime.h>
#include <cuda_fp16.h>
#include <cstdint>

#define KCODES 512
#define DCH 64
#define NPIX (32*64*64)        // 131072
#define TOTAL (NPIX*DCH)       // 8388608
#define TILE_M 128
#define NTILES (NPIX/TILE_M)   // 1024
#define TPB 256
#define REPAIR_T 1e-3f

// ---- smem byte offsets ----
#define SM_X    0           // fp16 X tile, 128 rows x 128B swizzled (16KB)
#define SM_E    16384       // fp16 E tile, 512 rows x 128B swizzled (64KB)
#define SM_E2V  81920       // float[512]
#define SM_X2V  83968       // float[128]
#define SM_RED  84480       // double[256]
#define SM_TD   0           // reuse X after MMA: float[2][128][3] = 3072B
#define SM_TI   3072        // int[2][128][3]   = 3072B
#define SMEM_BYTES 86528

__device__ double   g_partials[NTILES];
__device__ uint32_t gEimg[16384];   // 64KB preswizzled fp16 E image
__device__ float    gE2[KCODES];

__device__ __forceinline__ uint32_t smem_u32(const void* p) {
    uint32_t a;
    asm("{ .reg .u64 t; cvta.to.shared.u64 t, %1; cvt.u32.u64 %0, t; }" : "=r"(a) : "l"(p));
    return a;
}
__device__ __forceinline__ uint32_t sw(uint32_t row, uint32_t colb) {
    uint32_t off = row * 128u + colb;
    return off ^ ((off >> 3) & 0x70u);
}
__device__ __forceinline__ void ldsm4(uint32_t* r, uint32_t addr) {
    asm volatile("ldmatrix.sync.aligned.m8n8.x4.shared.b16 {%0,%1,%2,%3}, [%4];"
                 : "=r"(r[0]), "=r"(r[1]), "=r"(r[2]), "=r"(r[3]) : "r"(addr));
}
__device__ __forceinline__ void mma16816(float* c, const uint32_t* a, uint32_t b0, uint32_t b1) {
    asm volatile("mma.sync.aligned.m16n8k16.row.col.f32.f16.f16.f32 "
                 "{%0,%1,%2,%3},{%4,%5,%6,%7},{%8,%9},{%0,%1,%2,%3};"
                 : "+f"(c[0]), "+f"(c[1]), "+f"(c[2]), "+f"(c[3])
                 : "r"(a[0]), "r"(a[1]), "r"(a[2]), "r"(a[3]), "r"(b0), "r"(b1));
}
__device__ __forceinline__ bool better(float d, int i, float D, int I) {
    return (d < D) || (d == D && i < I);
}
// BRANCHLESS sorted top-3 insert: pure predicated selects, zero branches.
// (The branchy/guarded variant plausibly blew up ptxas reconvergence analysis
//  after full unrolling — R9 binary never produced any harness output.)
__device__ __forceinline__ void ins3(float d, int i, float* td, int* ti) {
    const bool b2 = better(d, i, td[2], ti[2]);
    const bool b1 = better(d, i, td[1], ti[1]);
    const bool b0 = better(d, i, td[0], ti[0]);
    td[2] = b1 ? td[1] : (b2 ? d : td[2]);
    ti[2] = b1 ? ti[1] : (b2 ? i : ti[2]);
    td[1] = b0 ? td[0] : (b1 ? d : td[1]);
    ti[1] = b0 ? ti[0] : (b1 ? i : ti[1]);
    td[0] = b0 ? d : td[0];
    ti[0] = b0 ? i : ti[0];
}

// ---- prep: build preswizzled fp16 E image + e2 (once per call) ----
__global__ void vq_prep(const float* __restrict__ W) {
    int r = blockIdx.x * blockDim.x + threadIdx.x;   // 4 x 128 = 512
    if (r >= KCODES) return;
    float e2 = 0.0f;
    #pragma unroll 8
    for (int c2 = 0; c2 < 32; c2++) {
        float2 wv = *(const float2*)(W + r * DCH + c2 * 2);
        e2 = __fadd_rn(e2, __fmaf_rn(wv.x, wv.x, __fmul_rn(wv.y, wv.y)));
        __half h0 = __float2half_rn(wv.x), h1 = __float2half_rn(wv.y);
        uint32_t pk = (uint32_t)__half_as_ushort(h0) | ((uint32_t)__half_as_ushort(h1) << 16);
        gEimg[sw((uint32_t)r, (uint32_t)c2 * 4) >> 2] = pk;
    }
    gE2[r] = e2;
}

__global__ void vq_dummy() {}

__global__ __launch_bounds__(TPB, 1)
void vq_mma(const float* __restrict__ lat, const float* __restrict__ W,
            float* __restrict__ out) {
    extern __shared__ char smem[];
    const uint32_t sb = smem_u32(smem);
    const int tid = threadIdx.x, wid = tid >> 5, lane = tid & 31;
    float* sE2v = (float*)(smem + SM_E2V);
    float* sX2v = (float*)(smem + SM_X2V);

    // ---- Phase 1: warps 0-3 build X fp16 tile + x2; warps 4-7 copy E image + e2 ----
    if (tid < 128) {
        const int r = tid;
        const int n0 = blockIdx.x * TILE_M + r;
        const int base = (n0 >> 12) << 18;
        const int p = n0 & 4095;
        float x2 = 0.0f;
        #pragma unroll 8
        for (int c = 0; c < DCH; c++) {
            float v = lat[base + (c << 12) + p];
            x2 = __fadd_rn(x2, __fmul_rn(v, v));   // sequential, reference order
            *(__half*)(smem + SM_X + sw(r, c * 2)) = __float2half_rn(v);
        }
        sX2v[r] = x2;
    } else {
        const int t = tid - 128;                   // 0..127
        float4* dst = (float4*)(smem + SM_E);
        const float4* src = (const float4*)gEimg;
        #pragma unroll
        for (int i = 0; i < 32; i++) dst[t + i * 128] = src[t + i * 128];
        #pragma unroll
        for (int i = 0; i < 4; i++) sE2v[t + i * 128] = gE2[t + i * 128];
    }
    __syncthreads();

    // ---- Phase 2: single-pass fp16 mma.sync, branchless per-thread top-3 on g = e2 - 2*dot ----
    const int mg = wid >> 1, ng = wid & 1;
    const int mbase = mg * 32, nbase = ng * 256;

    float td[4][3]; int ti[4][3];
    #pragma unroll
    for (int s = 0; s < 4; s++) {
        #pragma unroll
        for (int q = 0; q < 3; q++) { td[s][q] = 3.4e38f; ti[s][q] = 0x7FFFFFFF; }
    }

    const uint32_t aRow = (uint32_t)(mbase + (lane & 7) + (((lane >> 3) & 1) << 3));
    const uint32_t aKb  = (uint32_t)(((lane >> 4) & 1) << 4);
    const uint32_t bRowL = (uint32_t)((lane & 7) + (((lane >> 4) & 1) << 3));
    const uint32_t bKb  = (uint32_t)(((lane >> 3) & 1) << 4);

    #pragma unroll 1
    for (int chunk = 0; chunk < 4; chunk++) {
        const int cbase = nbase + chunk * 64;
        float acc[2][8][4];
        #pragma unroll
        for (int mt = 0; mt < 2; mt++)
            #pragma unroll
            for (int nt = 0; nt < 8; nt++)
                #pragma unroll
                for (int q = 0; q < 4; q++) acc[mt][nt][q] = 0.0f;

        #pragma unroll
        for (int ks = 0; ks < 4; ks++) {
            uint32_t a[8], b[16];
            const uint32_t kb = (uint32_t)(ks * 32);
            #pragma unroll
            for (int jj = 0; jj < 4; jj++)
                ldsm4(&b[jj * 4], sb + SM_E + sw((uint32_t)(cbase + 16 * jj) + bRowL, kb + bKb));
            ldsm4(&a[0], sb + SM_X + sw(aRow, kb + aKb));
            ldsm4(&a[4], sb + SM_X + sw(aRow + 16, kb + aKb));
            #pragma unroll
            for (int mt = 0; mt < 2; mt++)
                #pragma unroll
                for (int nt = 0; nt < 8; nt++) {
                    int j4 = (nt >> 1) * 4 + (nt & 1) * 2;
                    mma16816(acc[mt][nt], &a[mt * 4], b[j4], b[j4 + 1]);
                }
        }

        // epilogue: g = fl(e2 - 2*dot); branchless sorted top-3 per rowset
        #pragma unroll
        for (int mt = 0; mt < 2; mt++) {
            #pragma unroll
            for (int nt = 0; nt < 8; nt++) {
                const int col0 = cbase + 8 * nt + 2 * (lane & 3);
                const float e2a = sE2v[col0], e2b = sE2v[col0 + 1];
                float g00 = __fmaf_rn(-2.0f, acc[mt][nt][0], e2a);
                float g01 = __fmaf_rn(-2.0f, acc[mt][nt][1], e2b);
                float g10 = __fmaf_rn(-2.0f, acc[mt][nt][2], e2a);
                float g11 = __fmaf_rn(-2.0f, acc[mt][nt][3], e2b);
                ins3(g00, col0,     td[mt * 2],     ti[mt * 2]);
                ins3(g01, col0 + 1, td[mt * 2],     ti[mt * 2]);
                ins3(g10, col0,     td[mt * 2 + 1], ti[mt * 2 + 1]);
                ins3(g11, col0 + 1, td[mt * 2 + 1], ti[mt * 2 + 1]);
            }
        }
    }

    // ---- quad merge (lanes xor 1, 2 hold disjoint cols of same rows) ----
    #pragma unroll
    for (int st = 1; st <= 2; st <<= 1) {
        #pragma unroll
        for (int s = 0; s < 4; s++) {
            float od[3]; int oi[3];
            #pragma unroll
            for (int q = 0; q < 3; q++) {
                od[q] = __shfl_xor_sync(0xffffffffu, td[s][q], st);
                oi[q] = __shfl_xor_sync(0xffffffffu, ti[s][q], st);
            }
            #pragma unroll
            for (int q = 0; q < 3; q++) ins3(od[q], oi[q], td[s], ti[s]);
        }
    }

    __syncthreads();   // all ldsm X reads done -> X region reusable
    {
        float* sTd = (float*)(smem + SM_TD);
        int*   sTi = (int*)(smem + SM_TI);
        int s = lane & 3;
        int row = mbase + 8 * s + (lane >> 2);
        #pragma unroll
        for (int q = 0; q < 3; q++) {
            sTd[(ng * 128 + row) * 3 + q] = td[s][q];
            sTi[(ng * 128 + row) * 3 + q] = ti[s][q];
        }
    }
    __syncthreads();

    // ---- Phase 3: select (+ exact repair), gather, write, SSE ----
    double sse = 0.0;
    if (tid < 128) {
        const int r = tid;
        const int n0 = blockIdx.x * TILE_M + r;
        const int base = (n0 >> 12) << 18;
        const int p = n0 & 4095;
        const float x2 = sX2v[r];
        float* sTd = (float*)(smem + SM_TD);
        int*   sTi = (int*)(smem + SM_TI);

        float cd[6]; int ci[6];
        #pragma unroll
        for (int q = 0; q < 3; q++) {
            cd[q]     = sTd[r * 3 + q];         ci[q]     = sTi[r * 3 + q];
            cd[3 + q] = sTd[(128 + r) * 3 + q]; ci[3 + q] = sTi[(128 + r) * 3 + q];
        }
        float b1d = 3.4e38f, b2d = 3.4e38f; int b1i = 0x7FFFFFFF, b2i = 0x7FFFFFFF;
        #pragma unroll
        for (int q = 0; q < 6; q++) {
            bool bb = better(cd[q], ci[q], b1d, b1i);
            bool b2_ = better(cd[q], ci[q], b2d, b2i);
            b2d = bb ? b1d : (b2_ ? cd[q] : b2d);
            b2i = bb ? b1i : (b2_ ? ci[q] : b2i);
            b1d = bb ? cd[q] : b1d;
            b1i = bb ? ci[q] : b1i;
        }
        int i1 = b1i;
        if (b2d - b1d < REPAIR_T) {
            // exact fp32 reference-rounded dist over all 6 candidates
            float bestd = 3.4e38f; int besti = 0x7FFFFFFF;
            #pragma unroll 1
            for (int q = 0; q < 6; q++) {
                int k = ci[q];
                float dot = 0.0f;
                #pragma unroll 8
                for (int j = 0; j < DCH; j++)
                    dot = __fmaf_rn(lat[base + (j << 12) + p], W[k * DCH + j], dot);
                float d = __fmaf_rn(-2.0f, dot, __fadd_rn(x2, sE2v[k]));
                bool bb = better(d, k, bestd, besti);
                bestd = bb ? d : bestd;
                besti = bb ? k : besti;
            }
            i1 = besti;
        }
        #pragma unroll 8
        for (int j = 0; j < DCH; j++) {
            float q = W[i1 * DCH + j];
            float xv = lat[base + (j << 12) + p];
            out[base + (j << 12) + p] = q;
            float df = q - xv;
            sse += (double)__fmul_rn(df, df);
        }
    }

    double* sRed = (double*)(smem + SM_RED);
    sRed[tid] = sse;
    __syncthreads();
    #pragma unroll
    for (int o = TPB / 2; o > 0; o >>= 1) {
        if (tid < o) sRed[tid] += sRed[tid + o];
        __syncthreads();
    }
    if (tid == 0) g_partials[blockIdx.x] = sRed[0];
}

__global__ void vq_finish(float* __restrict__ out, int out_size) {
    __shared__ double s[256];
    int t = threadIdx.x;
    double v = 0.0;
    #pragma unroll
    for (int i = 0; i < NTILES / 256; i++) v += g_partials[t + i * 256];
    s[t] = v;
    __syncthreads();
    #pragma unroll
    for (int o = 128; o > 0; o >>= 1) {
        if (t < o) s[t] += s[t + o];
        __syncthreads();
    }
    if (t == 0) {
        float m = (float)(s[0] / (double)TOTAL);
        out[out_size - 1] = __fadd_rn(__fmul_rn(m, 0.25f), m);
    }
}

extern "C" void kernel_launch(void* const* d_in, const int* in_sizes, int n_in,
                              void* d_out, int out_size) {
    const float* lat = (const float*)d_in[0];
    const float* W   = (const float*)d_in[1];
    float* out = (float*)d_out;

    cudaFuncSetAttribute(vq_mma, cudaFuncAttributeMaxDynamicSharedMemorySize, SMEM_BYTES);

    // period-4 order so ncu (-s 5 -c 1) lands on vq_mma
    vq_prep<<<4, 128>>>(W);
    vq_mma<<<NTILES, TPB, SMEM_BYTES>>>(lat, W, out);
    vq_finish<<<1, 256>>>(out, out_size);
    vq_dummy<<<1, 32>>>();
}